// round 9
// baseline (speedup 1.0000x reference)
#include <cuda_runtime.h>
#include <cuda_bf16.h>

// WeightedAverage: out = sum_{3x3} v*exp(-v) / sum_{3x3} exp(-v)
// (softmax(-(local - x^2)) == softmax(-local): x^2 constant over patch axis;
//  zero padding contributes w=1 to denom, 0 to numer == loading v=0 OOB.)
//
// 2304 tiles of 128x128 (8 warps x 16 rows), grid = 592 = 148x4, grid-stride
// (single resident wave). Ring of 3 slots {float4 v, float vl, float vr},
// vector+halo prefetched 2 rows ahead (R8: removed exposed load->use).
// This round: 5 blocks/SM (<=51 regs) via pointer strength reduction +
// partial-sum reuse; sweep fully unrolled (R6: partial unroll kills MLP).

#define IMG_W   1536
#define IMG_H   1536
#define SROWS   16
#define WPB     8
#define TILES_X 12
#define TILES_Y 12
#define N_IMG   16
#define N_TILES (TILES_X * TILES_Y * N_IMG)   // 2304
#define NBLK    592                           // 148 SM x 4 resident blocks

struct Slot { float4 v; float vl, vr; };

__device__ __forceinline__ float4 f4add(const float4 a, const float4 b) {
    return make_float4(a.x + b.x, a.y + b.y, a.z + b.z, a.w + b.w);
}

__global__ __launch_bounds__(256, 5)
void wavg_kernel(const float* __restrict__ x, float* __restrict__ out) {
    const int lane = threadIdx.x & 31;
    const int wrp  = threadIdx.x >> 5;

    #pragma unroll 1
    for (int t = blockIdx.x; t < N_TILES; t += NBLK) {
        const int img_i = t / (TILES_X * TILES_Y);
        const int rem   = t - img_i * (TILES_X * TILES_Y);
        const int ty    = rem / TILES_X;
        const int tx    = rem - ty * TILES_X;

        const int col0 = tx * 128 + lane * 4;
        const int y0   = ty * 128 + wrp * SROWS;
        const size_t base = (size_t)img_i * (size_t)(IMG_W * IMG_H)
                          + (size_t)y0 * IMG_W + col0;
        const float* __restrict__ pin  = x   + base;   // row y0 of this lane
        float*       __restrict__ pout = out + base;

        const bool has_l = (col0 > 0);
        const bool has_r = (col0 + 4 < IMG_W);
        const bool has_t = (y0 > 0);

        // Load the row at pointer p (guarded warp-uniform by 'inb').
        auto loadrow = [&](const float* p, bool inb) -> Slot {
            Slot s;
            s.v = make_float4(0.f, 0.f, 0.f, 0.f);
            s.vl = 0.f; s.vr = 0.f;
            if (inb) {
                s.v = __ldg(reinterpret_cast<const float4*>(p));
                if (has_l) s.vl = __ldg(p - 1);
                if (has_r) s.vr = __ldg(p + 4);
            }
            return s;
        };

        // Horizontal 3-sums of w=exp(-v) and wv (pure register compute).
        auto hsum = [&](const Slot& s, float4& w, float4& wv) {
            const float w0 = __expf(-s.v.x);
            const float w1 = __expf(-s.v.y);
            const float w2 = __expf(-s.v.z);
            const float w3 = __expf(-s.v.w);
            const float wl = __expf(-s.vl);
            const float wr = __expf(-s.vr);
            const float pw = w1 + w2;
            w.x = wl + w0 + w1;
            w.y = w0 + pw;
            w.z = pw + w3;
            w.w = w2 + w3 + wr;
            const float al = wl * s.vl,  a0 = w0 * s.v.x, a1 = w1 * s.v.y;
            const float a2 = w2 * s.v.z, a3 = w3 * s.v.w, ar = wr * s.vr;
            const float pa = a1 + a2;
            wv.x = al + a0 + a1;
            wv.y = a0 + pa;
            wv.z = pa + a3;
            wv.w = a2 + a3 + ar;
        };

        Slot ring[3];

        // Prologue: rows y0-1, y0 consumed; rows y0+1, y0+2 in flight.
        Slot s_m1 = loadrow(pin - IMG_W, has_t);
        Slot s_0  = loadrow(pin, true);
        ring[0] = loadrow(pin + 1 * IMG_W, true);
        ring[1] = loadrow(pin + 2 * IMG_W, true);

        float4 hw0, hv0, hw1, hv1;
        hsum(s_m1, hw0, hv0);
        hsum(s_0,  hw1, hv1);
        float4 Aw  = f4add(hw0, hw1), Bw  = hw1;   // A = h(-1)+h(0), B = h(0)
        float4 Awv = f4add(hv0, hv1), Bwv = hv1;

        const float* pf = pin + 3 * IMG_W;   // prefetch pointer: row y0+3
        int yf = y0 + 3;

        #pragma unroll
        for (int k = 0; k < SROWS; k++) {
            // Prefetch row y0+k+3 into slot (k+2)%3.
            if (k < SROWS - 2)
                ring[(k + 2) % 3] = loadrow(pf, yf < IMG_H);
            pf += IMG_W; yf++;

            // Consume row y0+k+1 (slot k%3), loaded 2 iterations ago.
            float4 hw, hv;
            hsum(ring[k % 3], hw, hv);

            const float4 den = f4add(Aw,  hw);
            const float4 num = f4add(Awv, hv);
            float4 o;
            o.x = __fdividef(num.x, den.x);
            o.y = __fdividef(num.y, den.y);
            o.z = __fdividef(num.z, den.z);
            o.w = __fdividef(num.w, den.w);
            __stcs(reinterpret_cast<float4*>(pout), o);
            pout += IMG_W;

            Aw  = f4add(Bw,  hw);  Bw  = hw;
            Awv = f4add(Bwv, hv);  Bwv = hv;
        }
    }
}

extern "C" void kernel_launch(void* const* d_in, const int* in_sizes, int n_in,
                              void* d_out, int out_size) {
    const float* x = (const float*)d_in[0];
    float* out = (float*)d_out;
    wavg_kernel<<<NBLK, WPB * 32>>>(x, out);
}

// round 10
// speedup vs baseline: 1.2262x; 1.2262x over previous
#include <cuda_runtime.h>
#include <cuda_bf16.h>

// WeightedAverage: out = sum_{3x3} v*exp(-v) / sum_{3x3} exp(-v)
// (softmax(-(local - x^2)) == softmax(-local): x^2 constant over patch axis;
//  zero padding contributes w=1 to denom, 0 to numer == loading v=0 OOB.)
//
// R8 structure (known-good 53.8us) with SROWS=32:
// 1152 tiles of 128x256 (8 warps x 32 rows), grid = 592 = 148x4, grid-stride
// (single resident wave). Ring of 3 slots {float4 v, float vl, float vr},
// vector+halo prefetched together 2 rows ahead. Sweep FULLY unrolled
// (R6: partial unroll kills MLP; R9: reg-capping kills MLP — regs float ~64).

#define IMG_W   1536
#define IMG_H   1536
#define SROWS   32
#define WPB     8
#define TILES_X 12
#define TILES_Y 6
#define N_IMG   16
#define N_TILES (TILES_X * TILES_Y * N_IMG)   // 1152
#define NBLK    592                           // 148 SM x 4 resident blocks

struct Slot { float4 v; float vl, vr; };

__device__ __forceinline__ float4 f4add(const float4 a, const float4 b) {
    return make_float4(a.x + b.x, a.y + b.y, a.z + b.z, a.w + b.w);
}

__global__ __launch_bounds__(256, 4)
void wavg_kernel(const float* __restrict__ x, float* __restrict__ out) {
    const int lane = threadIdx.x & 31;
    const int wrp  = threadIdx.x >> 5;

    #pragma unroll 1
    for (int t = blockIdx.x; t < N_TILES; t += NBLK) {
        const int img_i = t / (TILES_X * TILES_Y);
        const int rem   = t - img_i * (TILES_X * TILES_Y);
        const int ty    = rem / TILES_X;
        const int tx    = rem - ty * TILES_X;

        const int col0 = tx * 128 + lane * 4;
        const int y0   = ty * 256 + wrp * SROWS;
        const size_t ibase = (size_t)img_i * (size_t)(IMG_W * IMG_H);
        const float* __restrict__ img = x + ibase;
        float* __restrict__ optr = out + ibase + (size_t)y0 * IMG_W + col0;

        const bool has_l = (col0 > 0);
        const bool has_r = (col0 + 4 < IMG_W);

        Slot ring[3];

        // Load row y: float4 plus both halo scalars, together.
        auto loadrow = [&](int y) -> Slot {
            Slot s;
            s.v = make_float4(0.f, 0.f, 0.f, 0.f);
            s.vl = 0.f; s.vr = 0.f;
            if ((unsigned)y < (unsigned)IMG_H) {
                const float* p = img + (size_t)y * IMG_W + col0;
                s.v = __ldg(reinterpret_cast<const float4*>(p));
                if (has_l) s.vl = __ldg(p - 1);
                if (has_r) s.vr = __ldg(p + 4);
            }
            return s;
        };

        // Horizontal 3-sums of w=exp(-v) and wv for one row (pure compute).
        auto hsum = [&](const Slot& s, float4& w, float4& wv) {
            const float w0 = __expf(-s.v.x);
            const float w1 = __expf(-s.v.y);
            const float w2 = __expf(-s.v.z);
            const float w3 = __expf(-s.v.w);
            const float wl = __expf(-s.vl);
            const float wr = __expf(-s.vr);
            w.x = wl + w0 + w1;
            w.y = w0 + w1 + w2;
            w.z = w1 + w2 + w3;
            w.w = w2 + w3 + wr;
            const float al = wl * s.vl,  a0 = w0 * s.v.x, a1 = w1 * s.v.y;
            const float a2 = w2 * s.v.z, a3 = w3 * s.v.w, ar = wr * s.vr;
            wv.x = al + a0 + a1;
            wv.y = a0 + a1 + a2;
            wv.z = a1 + a2 + a3;
            wv.w = a2 + a3 + ar;
        };

        // Prologue. slot(row) = (row - y0 + 2) % 3.
        Slot s_m1 = loadrow(y0 - 1);
        Slot s_0  = loadrow(y0);
        ring[0] = loadrow(y0 + 1);   // row y0+1 -> slot 0
        ring[1] = loadrow(y0 + 2);   // row y0+2 -> slot 1

        float4 hw0, hv0, hw1, hv1;
        hsum(s_m1, hw0, hv0);
        hsum(s_0,  hw1, hv1);
        float4 Aw  = f4add(hw0, hw1), Bw  = hw1;   // A = h(-1)+h(0), B = h(0)
        float4 Awv = f4add(hv0, hv1), Bwv = hv1;

        #pragma unroll
        for (int k = 0; k < SROWS; k++) {
            // Prefetch row y0+k+3 into slot (k+2)%3 (freed: row y0+k consumed
            // at k-1). Live rows k+1..k+3 occupy the 3 slots.
            if (k < SROWS - 2)
                ring[(k + 2) % 3] = loadrow(y0 + k + 3);
            // Consume row y0+k+1 (slot k%3), loaded 2 iterations ago.
            float4 hw, hv;
            hsum(ring[k % 3], hw, hv);

            const float4 den = f4add(Aw,  hw);
            const float4 num = f4add(Awv, hv);
            float4 o;
            o.x = __fdividef(num.x, den.x);
            o.y = __fdividef(num.y, den.y);
            o.z = __fdividef(num.z, den.z);
            o.w = __fdividef(num.w, den.w);
            __stcs(reinterpret_cast<float4*>(optr), o);
            optr += IMG_W;

            Aw  = f4add(Bw,  hw);  Bw  = hw;
            Awv = f4add(Bwv, hv);  Bwv = hv;
        }
    }
}

extern "C" void kernel_launch(void* const* d_in, const int* in_sizes, int n_in,
                              void* d_out, int out_size) {
    const float* x = (const float*)d_in[0];
    float* out = (float*)d_out;
    wavg_kernel<<<NBLK, WPB * 32>>>(x, out);
}